// round 12
// baseline (speedup 1.0000x reference)
#include <cuda_runtime.h>
#include <cuda_bf16.h>
#include <math.h>
#include <stdint.h>

// ---------------------------------------------------------------------------
// LNN — collapsed leaky-integrator MLP on tensor cores via mma.sync (bf16),
// fp32 emulated with 3-term hi/lo split: A*B ~= Ahi*Bhi + Alo*Bhi + Ahi*Blo.
// CTA tile 128x256, 512 threads (16 warps, 4Mx4N, warp tile 32x64),
// 3-stage cp.async ring (wait_group 1 -> loads run two chunks ahead).
//
//   d1    = relu(x @ W1^T + b1)            GEMM1 (epilogue: relu + bf16-split)
//   s2acc = scan(d1 @ W2^T, b2)            GEMM2 (epilogue: T-step scan + split)
//   part  = split-K s2acc @ W3^T           GEMM3 (KSPLIT=4, raw fp32 partials)
//   out   = (1-b3^T) b3 + sum_z part[z]    reduce
// ---------------------------------------------------------------------------

#define MODE_RELU 0
#define MODE_SCAN 1
#define MODE_PART 2
#define KSPLIT 4

typedef __nv_bfloat16 bf16;

// ----- device scratch (no allocations allowed) -----
#define AL __align__(256)
__device__ AL bf16 g_xhi [1024*2048], g_xlo [1024*2048];
__device__ AL bf16 g_w1hi[4096*2048], g_w1lo[4096*2048];
__device__ AL bf16 g_w2hi[4096*4096], g_w2lo[4096*4096];
__device__ AL bf16 g_w3hi[1024*4096], g_w3lo[1024*4096];
__device__ AL bf16 g_d1hi[1024*4096], g_d1lo[1024*4096];
__device__ AL bf16 g_s2hi[1024*4096], g_s2lo[1024*4096];
__device__ AL float g_part[KSPLIT*1024*1024];

__device__ __forceinline__ float sigmoid_acc(float v) { return 1.0f / (1.0f + expf(-v)); }

__device__ __forceinline__ uint32_t smem_u32(const void* p) {
    uint32_t a;
    asm("{ .reg .u64 t; cvta.to.shared.u64 t, %1; cvt.u32.u64 %0, t; }" : "=r"(a) : "l"(p));
    return a;
}

__device__ __forceinline__ void ldsm_x4(uint32_t* r, uint32_t addr) {
    asm volatile("ldmatrix.sync.aligned.m8n8.x4.shared.b16 {%0,%1,%2,%3}, [%4];"
                 : "=r"(r[0]), "=r"(r[1]), "=r"(r[2]), "=r"(r[3]) : "r"(addr));
}

__device__ __forceinline__ void mma_bf16(float* c, const uint32_t* a, const uint32_t* b) {
    asm volatile("mma.sync.aligned.m16n8k16.row.col.f32.bf16.bf16.f32 "
                 "{%0,%1,%2,%3}, {%4,%5,%6,%7}, {%8,%9}, {%0,%1,%2,%3};"
                 : "+f"(c[0]), "+f"(c[1]), "+f"(c[2]), "+f"(c[3])
                 : "r"(a[0]), "r"(a[1]), "r"(a[2]), "r"(a[3]), "r"(b[0]), "r"(b[1]));
}

__device__ __forceinline__ void cpa16(uint32_t dst, const void* src) {
    asm volatile("cp.async.cg.shared.global [%0], [%1], 16;"
                 :: "r"(dst), "l"(src) : "memory");
}
#define CP_COMMIT() asm volatile("cp.async.commit_group;" ::: "memory")
#define CP_WAIT0()  asm volatile("cp.async.wait_group 0;" ::: "memory")
#define CP_WAIT1()  asm volatile("cp.async.wait_group 1;" ::: "memory")

// SW64-style swizzle: row stride 64B, 16B chunk c xored by (r>>1)&3.
__device__ __forceinline__ uint32_t sw_off(int r, int c) {
    return (uint32_t)(r * 64 + ((c ^ ((r >> 1) & 3)) << 4));
}

// ----- fp32 -> bf16 hi/lo split, 4 tensors in one launch -----
__global__ void __launch_bounds__(256)
convert_split4(const float* __restrict__ s0, bf16* __restrict__ h0, bf16* __restrict__ l0, int nb0,
               const float* __restrict__ s1, bf16* __restrict__ h1, bf16* __restrict__ l1, int nb1,
               const float* __restrict__ s2, bf16* __restrict__ h2, bf16* __restrict__ l2, int nb2,
               const float* __restrict__ s3, bf16* __restrict__ h3, bf16* __restrict__ l3, int nb3)
{
    int b = blockIdx.x;
    const float* src; bf16 *hi, *lo;
    if (b < nb0)                    { src = s0; hi = h0; lo = l0; }
    else if (b < nb0 + nb1)         { src = s1; hi = h1; lo = l1; b -= nb0; }
    else if (b < nb0 + nb1 + nb2)   { src = s2; hi = h2; lo = l2; b -= nb0 + nb1; }
    else                            { src = s3; hi = h3; lo = l3; b -= nb0 + nb1 + nb2; }

    int i = (b * 256 + threadIdx.x) * 8;
    float4 v0 = *(const float4*)(src + i);
    float4 v1 = *(const float4*)(src + i + 4);
    float v[8] = {v0.x, v0.y, v0.z, v0.w, v1.x, v1.y, v1.z, v1.w};
    uint32_t hw[8], lw[8];
#pragma unroll
    for (int q = 0; q < 8; q++) {
        bf16 h = __float2bfloat16(v[q]);
        bf16 l = __float2bfloat16(v[q] - __bfloat162float(h));
        hw[q] = __bfloat16_as_ushort(h);
        lw[q] = __bfloat16_as_ushort(l);
    }
    uint4 hp, lp;
    hp.x = hw[0] | (hw[1] << 16); hp.y = hw[2] | (hw[3] << 16);
    hp.z = hw[4] | (hw[5] << 16); hp.w = hw[6] | (hw[7] << 16);
    lp.x = lw[0] | (lw[1] << 16); lp.y = lw[2] | (lw[3] << 16);
    lp.z = lw[4] | (lw[5] << 16); lp.w = lw[6] | (lw[7] << 16);
    *(uint4*)(hi + i) = hp;
    *(uint4*)(lo + i) = lp;
}

// ---------------------------------------------------------------------------
// Tensor-core GEMM:  C[M,N] = A[M,K] @ B[N,K]^T, BM=128, BN=256, BK=32,
// 512 threads = 16 warps (4Mx4N), warp tile 32x64. mma.m16n8k16 bf16 x3,
// fp32 acc. 3-stage cp.async ring (48 KB/stage, wait_group 1).
// ---------------------------------------------------------------------------
__global__ void __launch_bounds__(512)
tc_gemm(const bf16* __restrict__ Ahi, const bf16* __restrict__ Alo,
        const bf16* __restrict__ Bhi, const bf16* __restrict__ Blo,
        const float* __restrict__ bias, float* __restrict__ Cf,
        bf16* __restrict__ OutHi, bf16* __restrict__ OutLo,
        int M, int N, int K, int lda, int mode,
        const float* __restrict__ b_taus, const int* __restrict__ Tp)
{
    extern __shared__ __align__(128) char smem[];
    const uint32_t sb = smem_u32(smem);
    constexpr uint32_t STG = 49152;     // 8K AHI + 8K ALO + 16K BHI + 16K BLO
    constexpr uint32_t S_AHI = 0, S_ALO = 8192, S_BHI = 16384, S_BLO = 32768;

    const int tid = threadIdx.x;
    const int wid = tid >> 5;
    const int lid = tid & 31;
    const int warpM = wid & 3;          // 4 M-slices of 32 rows
    const int warpN = wid >> 2;         // 4 N-slices of 64 cols

    const int m0 = blockIdx.y * 128;
    const int n0 = blockIdx.x * 256;
    const int kbase = blockIdx.z * K;   // split-K slab

    // loader: 512 threads, 16B chunks; r0 covers 128 A-rows / 2x128 B-rows
    const int r0 = tid >> 2, c0 = tid & 3;
    const size_t s128 = (size_t)128 * lda;
    const bf16* gAh = Ahi + (size_t)(m0 + r0) * lda + kbase + c0 * 8;
    const bf16* gAl = Alo + (size_t)(m0 + r0) * lda + kbase + c0 * 8;
    const bf16* gBh = Bhi + (size_t)(n0 + r0) * lda + kbase + c0 * 8;
    const bf16* gBl = Blo + (size_t)(n0 + r0) * lda + kbase + c0 * 8;
    const uint32_t soA  = sw_off(r0, c0);
    const uint32_t soB0 = soA, soB1 = sw_off(r0 + 128, c0);

    // ldmatrix per-thread addressing
    const int id = lid >> 3, rin = lid & 7;
    const int arow = warpM * 32 + (id & 1) * 8 + rin;
    const int acol = (id >> 1);
    const int brow = warpN * 64 + (id >> 1) * 8 + rin;
    const int bcol = (id & 1);

    float acc[2][8][4];
#pragma unroll
    for (int mt = 0; mt < 2; mt++)
#pragma unroll
        for (int nf = 0; nf < 8; nf++)
#pragma unroll
            for (int q = 0; q < 4; q++) acc[mt][nf][q] = 0.0f;

    const int NCH = K / 32;

    auto ISSUE = [&](int ch) {
        const int kc = ch * 32;
        const uint32_t dst = sb + (uint32_t)(ch % 3) * STG;
        cpa16(dst + S_AHI + soA,  gAh + kc);
        cpa16(dst + S_ALO + soA,  gAl + kc);
        cpa16(dst + S_BHI + soB0, gBh + kc);
        cpa16(dst + S_BHI + soB1, gBh + kc + s128);
        cpa16(dst + S_BLO + soB0, gBl + kc);
        cpa16(dst + S_BLO + soB1, gBl + kc + s128);
        CP_COMMIT();
    };

    ISSUE(0);
    if (NCH > 1) ISSUE(1);

    for (int ch = 0; ch < NCH; ch++) {
        if (ch + 1 < NCH) { CP_WAIT1(); } else { CP_WAIT0(); }
        __syncthreads();
        if (ch + 2 < NCH) ISSUE(ch + 2);

        const uint32_t bufb = sb + (uint32_t)(ch % 3) * STG;

#pragma unroll
        for (int kk = 0; kk < 2; kk++) {
            uint32_t ah[2][4], al[2][4];
#pragma unroll
            for (int mt = 0; mt < 2; mt++) {
                uint32_t ao = sw_off(arow + mt * 16, acol + kk * 2);
                ldsm_x4(ah[mt], bufb + S_AHI + ao);
                ldsm_x4(al[mt], bufb + S_ALO + ao);
            }
#pragma unroll
            for (int g = 0; g < 2; g++) {   // two groups of 2 n16-tiles
                uint32_t bh[2][4], bl[2][4];
#pragma unroll
                for (int j = 0; j < 2; j++) {
                    uint32_t bo = sw_off(brow + (g * 2 + j) * 16, bcol + kk * 2);
                    ldsm_x4(bh[j], bufb + S_BHI + bo);
                    ldsm_x4(bl[j], bufb + S_BLO + bo);
                }
#pragma unroll
                for (int mt = 0; mt < 2; mt++)
#pragma unroll
                    for (int j = 0; j < 2; j++)
#pragma unroll
                        for (int h = 0; h < 2; h++) {
                            float* c = acc[mt][(g * 2 + j) * 2 + h];
                            mma_bf16(c, ah[mt], &bh[j][h * 2]);   // hi*hi
                            mma_bf16(c, al[mt], &bh[j][h * 2]);   // lo*hi
                            mma_bf16(c, ah[mt], &bl[j][h * 2]);   // hi*lo
                        }
            }
        }
    }

    // ---- epilogue (register fragments) ----
    float beta1 = 0.f, beta2 = 0.f, wt0 = 0.f, invb3 = 0.f, om2 = 0.f;
    int T = 0;
    if (mode == MODE_SCAN) {
        beta1 = sigmoid_acc(b_taus[0]);
        beta2 = sigmoid_acc(b_taus[1]);
        float beta3 = sigmoid_acc(b_taus[2]);
        T     = *Tp;
        invb3 = 1.0f / beta3;
        om2   = 1.0f - beta2;
        wt0   = (1.0f - beta3) * powf(beta3, (float)(T - 1));
    }

    const int mrow = m0 + warpM * 32 + (lid >> 2);
    const int ncol = n0 + warpN * 64 + (lid & 3) * 2;

#pragma unroll
    for (int mt = 0; mt < 2; mt++) {
#pragma unroll
        for (int nf = 0; nf < 8; nf++) {
            const int col = ncol + nf * 8;
#pragma unroll
            for (int pair = 0; pair < 2; pair++) {
                const int row = mrow + mt * 16 + pair * 8;
                float v0 = acc[mt][nf][pair * 2 + 0];
                float v1 = acc[mt][nf][pair * 2 + 1];
                size_t base = (size_t)row * N + col;

                if (mode == MODE_PART) {
                    float* Cz = Cf + (size_t)blockIdx.z * M * N;
                    *(float2*)(Cz + base) = make_float2(v0, v1);
                    continue;
                }

                float bv0 = __ldg(&bias[col]), bv1 = __ldg(&bias[col + 1]);
                float o0, o1;
                if (mode == MODE_RELU) {
                    o0 = fmaxf(v0 + bv0, 0.0f);
                    o1 = fmaxf(v1 + bv1, 0.0f);
                } else { // MODE_SCAN
                    float s20 = 0.f, a0 = 0.f, s21 = 0.f, a1 = 0.f;
                    float bp = beta1, wt = wt0;
                    for (int t = 0; t < T; t++) {
                        float c1m = 1.0f - bp;
                        float d0 = fmaxf(fmaf(c1m, v0, bv0), 0.0f);
                        float d1 = fmaxf(fmaf(c1m, v1, bv1), 0.0f);
                        s20 = fmaf(beta2, s20, om2 * d0);
                        s21 = fmaf(beta2, s21, om2 * d1);
                        a0 = fmaf(wt, s20, a0);
                        a1 = fmaf(wt, s21, a1);
                        bp *= beta1;
                        wt *= invb3;
                    }
                    o0 = a0; o1 = a1;
                }
                bf16 h0 = __float2bfloat16(o0), h1 = __float2bfloat16(o1);
                bf16 l0 = __float2bfloat16(o0 - __bfloat162float(h0));
                bf16 l1 = __float2bfloat16(o1 - __bfloat162float(h1));
                uint32_t hp = (uint32_t)__bfloat16_as_ushort(h0) |
                              ((uint32_t)__bfloat16_as_ushort(h1) << 16);
                uint32_t lp = (uint32_t)__bfloat16_as_ushort(l0) |
                              ((uint32_t)__bfloat16_as_ushort(l1) << 16);
                *(uint32_t*)(OutHi + base) = hp;
                *(uint32_t*)(OutLo + base) = lp;
            }
        }
    }
}

// out[i] = (1 - beta3^T) * b3[i % N] + sum_z part[z][i]
__global__ void __launch_bounds__(256)
reduce_out(const float* __restrict__ part, const float* __restrict__ b3,
           float* __restrict__ out, int total, int N,
           const float* __restrict__ b_taus, const int* __restrict__ Tp)
{
    int i = (blockIdx.x * blockDim.x + threadIdx.x) * 4;
    if (i >= total) return;
    float beta3  = sigmoid_acc(b_taus[2]);
    float bscale = 1.0f - powf(beta3, (float)(*Tp));
    float4 bb = *(const float4*)(b3 + (i % N));
    float4 s  = make_float4(bscale * bb.x, bscale * bb.y, bscale * bb.z, bscale * bb.w);
#pragma unroll
    for (int z = 0; z < KSPLIT; z++) {
        float4 p = *(const float4*)(part + (size_t)z * total + i);
        s.x += p.x; s.y += p.y; s.z += p.z; s.w += p.w;
    }
    *(float4*)(out + i) = s;
}

extern "C" void kernel_launch(void* const* d_in, const int* in_sizes, int n_in,
                              void* d_out, int out_size)
{
    const float* x     = (const float*)d_in[0];
    const float* W1    = (const float*)d_in[1];
    const float* b1    = (const float*)d_in[2];
    const float* W2    = (const float*)d_in[3];
    const float* b2    = (const float*)d_in[4];
    const float* W3    = (const float*)d_in[5];
    const float* b3    = (const float*)d_in[6];
    const float* btaus = (const float*)d_in[7];
    const int*   Tp    = (const int*)d_in[8];

    const int H1    = in_sizes[2];
    const int D_IN  = in_sizes[1] / H1;
    const int B     = in_sizes[0] / D_IN;
    const int H2    = in_sizes[4];
    const int D_OUT = in_sizes[6];

    bf16 *xhi, *xlo, *w1hi, *w1lo, *w2hi, *w2lo, *w3hi, *w3lo;
    bf16 *d1hi, *d1lo, *s2hi, *s2lo;
    float* part;
    cudaGetSymbolAddress((void**)&xhi,  g_xhi);  cudaGetSymbolAddress((void**)&xlo,  g_xlo);
    cudaGetSymbolAddress((void**)&w1hi, g_w1hi); cudaGetSymbolAddress((void**)&w1lo, g_w1lo);
    cudaGetSymbolAddress((void**)&w2hi, g_w2hi); cudaGetSymbolAddress((void**)&w2lo, g_w2lo);
    cudaGetSymbolAddress((void**)&w3hi, g_w3hi); cudaGetSymbolAddress((void**)&w3lo, g_w3lo);
    cudaGetSymbolAddress((void**)&d1hi, g_d1hi); cudaGetSymbolAddress((void**)&d1lo, g_d1lo);
    cudaGetSymbolAddress((void**)&s2hi, g_s2hi); cudaGetSymbolAddress((void**)&s2lo, g_s2lo);
    cudaGetSymbolAddress((void**)&part, g_part);

    float* out = (float*)d_out;

    const int SMEM = 3 * 49152;   // 147,456 B
    cudaFuncSetAttribute(tc_gemm, cudaFuncAttributeMaxDynamicSharedMemorySize, SMEM);

    // 0) split all inputs into bf16 hi/lo, single launch
    {
        int nb0 = (B * D_IN)   / 2048;
        int nb1 = (H1 * D_IN)  / 2048;
        int nb2 = (H2 * H1)    / 2048;
        int nb3 = (D_OUT * H2) / 2048;
        convert_split4<<<nb0 + nb1 + nb2 + nb3, 256>>>(
            x,  xhi,  xlo,  nb0,
            W1, w1hi, w1lo, nb1,
            W2, w2hi, w2lo, nb2,
            W3, w3hi, w3lo, nb3);
    }
    // 1) d1 = relu(x @ W1^T + b1) -> bf16 hi/lo           [B, H1]
    {
        dim3 grid(H1 / 256, B / 128, 1);
        tc_gemm<<<grid, 512, SMEM>>>(xhi, xlo, w1hi, w1lo, b1, nullptr, d1hi, d1lo,
                                     B, H1, D_IN, D_IN, MODE_RELU, btaus, Tp);
    }
    // 2) s2acc = scan(d1 @ W2^T, b2) -> bf16 hi/lo        [B, H2]
    {
        dim3 grid(H2 / 256, B / 128, 1);
        tc_gemm<<<grid, 512, SMEM>>>(d1hi, d1lo, w2hi, w2lo, b2, nullptr, s2hi, s2lo,
                                     B, H2, H1, H1, MODE_SCAN, btaus, Tp);
    }
    // 3) split-K partials of s2acc @ W3^T                 [KSPLIT][B, D_OUT]
    {
        dim3 grid(D_OUT / 256, B / 128, KSPLIT);
        tc_gemm<<<grid, 512, SMEM>>>(s2hi, s2lo, w3hi, w3lo, nullptr, part, nullptr, nullptr,
                                     B, D_OUT, H2 / KSPLIT, H2, MODE_PART, btaus, Tp);
    }
    // 4) out = (1-b3^T) b3 + sum partials                 [B, D_OUT]
    {
        int total = B * D_OUT;
        reduce_out<<<(total / 4 + 255) / 256, 256>>>(part, b3, out, total, D_OUT, btaus, Tp);
    }
    (void)n_in; (void)out_size;
}

// round 14
// speedup vs baseline: 1.1221x; 1.1221x over previous
#include <cuda_runtime.h>
#include <cuda_bf16.h>
#include <math.h>
#include <stdint.h>

// ---------------------------------------------------------------------------
// LNN — collapsed leaky-integrator MLP on tensor cores via mma.sync (bf16),
// fp32 emulated with 3-term hi/lo split: A*B ~= Ahi*Bhi + Alo*Bhi + Ahi*Blo.
// CTA tile 128x256, 512 threads (16 warps, 4Mx4N, warp tile 32x64),
// BK=64 chunks (halved barrier count), 2-stage cp.async (96 KB/stage).
// Convert kernel identical to the proven R11/R12 version (8 elems/thread).
//
//   d1    = relu(x @ W1^T + b1)            GEMM1 (epilogue: relu + bf16-split)
//   s2acc = scan(d1 @ W2^T, b2)            GEMM2 (epilogue: T-step scan + split)
//   part  = split-K s2acc @ W3^T           GEMM3 (KSPLIT=4, raw fp32 partials)
//   out   = (1-b3^T) b3 + sum_z part[z]    reduce
// ---------------------------------------------------------------------------

#define MODE_RELU 0
#define MODE_SCAN 1
#define MODE_PART 2
#define KSPLIT 4

typedef __nv_bfloat16 bf16;

// ----- device scratch (no allocations allowed) -----
#define AL __align__(256)
__device__ AL bf16 g_xhi [1024*2048], g_xlo [1024*2048];
__device__ AL bf16 g_w1hi[4096*2048], g_w1lo[4096*2048];
__device__ AL bf16 g_w2hi[4096*4096], g_w2lo[4096*4096];
__device__ AL bf16 g_w3hi[1024*4096], g_w3lo[1024*4096];
__device__ AL bf16 g_d1hi[1024*4096], g_d1lo[1024*4096];
__device__ AL bf16 g_s2hi[1024*4096], g_s2lo[1024*4096];
__device__ AL float g_part[KSPLIT*1024*1024];

__device__ __forceinline__ float sigmoid_acc(float v) { return 1.0f / (1.0f + expf(-v)); }

__device__ __forceinline__ uint32_t smem_u32(const void* p) {
    uint32_t a;
    asm("{ .reg .u64 t; cvta.to.shared.u64 t, %1; cvt.u32.u64 %0, t; }" : "=r"(a) : "l"(p));
    return a;
}

__device__ __forceinline__ void ldsm_x4(uint32_t* r, uint32_t addr) {
    asm volatile("ldmatrix.sync.aligned.m8n8.x4.shared.b16 {%0,%1,%2,%3}, [%4];"
                 : "=r"(r[0]), "=r"(r[1]), "=r"(r[2]), "=r"(r[3]) : "r"(addr));
}

__device__ __forceinline__ void mma_bf16(float* c, const uint32_t* a, const uint32_t* b) {
    asm volatile("mma.sync.aligned.m16n8k16.row.col.f32.bf16.bf16.f32 "
                 "{%0,%1,%2,%3}, {%4,%5,%6,%7}, {%8,%9}, {%0,%1,%2,%3};"
                 : "+f"(c[0]), "+f"(c[1]), "+f"(c[2]), "+f"(c[3])
                 : "r"(a[0]), "r"(a[1]), "r"(a[2]), "r"(a[3]), "r"(b[0]), "r"(b[1]));
}

__device__ __forceinline__ void cpa16(uint32_t dst, const void* src) {
    asm volatile("cp.async.cg.shared.global [%0], [%1], 16;"
                 :: "r"(dst), "l"(src) : "memory");
}
#define CP_COMMIT() asm volatile("cp.async.commit_group;" ::: "memory")
#define CP_WAIT0()  asm volatile("cp.async.wait_group 0;" ::: "memory")

// SW128 swizzle for 128B rows: 16B chunk c xored by (r & 7).
__device__ __forceinline__ uint32_t sw_off(int r, int c) {
    return (uint32_t)(r * 128 + ((c ^ (r & 7)) << 4));
}

// ----- fp32 -> bf16 hi/lo split, 4 tensors in one launch (8 elems/thread) -----
__global__ void __launch_bounds__(256)
convert_split4(const float* __restrict__ s0, bf16* __restrict__ h0, bf16* __restrict__ l0, int nb0,
               const float* __restrict__ s1, bf16* __restrict__ h1, bf16* __restrict__ l1, int nb1,
               const float* __restrict__ s2, bf16* __restrict__ h2, bf16* __restrict__ l2, int nb2,
               const float* __restrict__ s3, bf16* __restrict__ h3, bf16* __restrict__ l3, int nb3)
{
    int b = blockIdx.x;
    const float* src; bf16 *hi, *lo;
    if (b < nb0)                    { src = s0; hi = h0; lo = l0; }
    else if (b < nb0 + nb1)         { src = s1; hi = h1; lo = l1; b -= nb0; }
    else if (b < nb0 + nb1 + nb2)   { src = s2; hi = h2; lo = l2; b -= nb0 + nb1; }
    else                            { src = s3; hi = h3; lo = l3; b -= nb0 + nb1 + nb2; }

    int i = (b * 256 + threadIdx.x) * 8;
    float4 v0 = *(const float4*)(src + i);
    float4 v1 = *(const float4*)(src + i + 4);
    float v[8] = {v0.x, v0.y, v0.z, v0.w, v1.x, v1.y, v1.z, v1.w};
    uint32_t hw[8], lw[8];
#pragma unroll
    for (int q = 0; q < 8; q++) {
        bf16 h = __float2bfloat16(v[q]);
        bf16 l = __float2bfloat16(v[q] - __bfloat162float(h));
        hw[q] = __bfloat16_as_ushort(h);
        lw[q] = __bfloat16_as_ushort(l);
    }
    uint4 hp, lp;
    hp.x = hw[0] | (hw[1] << 16); hp.y = hw[2] | (hw[3] << 16);
    hp.z = hw[4] | (hw[5] << 16); hp.w = hw[6] | (hw[7] << 16);
    lp.x = lw[0] | (lw[1] << 16); lp.y = lw[2] | (lw[3] << 16);
    lp.z = lw[4] | (lw[5] << 16); lp.w = lw[6] | (lw[7] << 16);
    *(uint4*)(hi + i) = hp;
    *(uint4*)(lo + i) = lp;
}

// ---------------------------------------------------------------------------
// Tensor-core GEMM:  C[M,N] = A[M,K] @ B[N,K]^T, BM=128, BN=256, BK=64,
// 512 threads = 16 warps (4Mx4N), warp tile 32x64. mma.m16n8k16 bf16 x3,
// fp32 acc. 2-stage cp.async (96 KB/stage), one barrier per 64-wide K chunk.
// ---------------------------------------------------------------------------
__global__ void __launch_bounds__(512)
tc_gemm(const bf16* __restrict__ Ahi, const bf16* __restrict__ Alo,
        const bf16* __restrict__ Bhi, const bf16* __restrict__ Blo,
        const float* __restrict__ bias, float* __restrict__ Cf,
        bf16* __restrict__ OutHi, bf16* __restrict__ OutLo,
        int M, int N, int K, int lda, int mode,
        const float* __restrict__ b_taus, const int* __restrict__ Tp)
{
    extern __shared__ __align__(128) char smem[];
    const uint32_t sb = smem_u32(smem);
    constexpr uint32_t STG = 98304;     // 16K AHI + 16K ALO + 32K BHI + 32K BLO
    constexpr uint32_t S_AHI = 0, S_ALO = 16384, S_BHI = 32768, S_BLO = 65536;

    const int tid = threadIdx.x;
    const int wid = tid >> 5;
    const int lid = tid & 31;
    const int warpM = wid & 3;          // 4 M-slices of 32 rows
    const int warpN = wid >> 2;         // 4 N-slices of 64 cols

    const int m0 = blockIdx.y * 128;
    const int n0 = blockIdx.x * 256;
    const int kbase = blockIdx.z * K;   // split-K slab

    // loader: 512 threads, rows of 128B (8 x 16B chunks)
    const int r0 = tid >> 3, c0 = tid & 7;   // r0: 0..63
    const size_t s64 = (size_t)64 * lda;
    const bf16* gAh = Ahi + (size_t)(m0 + r0) * lda + kbase + c0 * 8;
    const bf16* gAl = Alo + (size_t)(m0 + r0) * lda + kbase + c0 * 8;
    const bf16* gBh = Bhi + (size_t)(n0 + r0) * lda + kbase + c0 * 8;
    const bf16* gBl = Blo + (size_t)(n0 + r0) * lda + kbase + c0 * 8;
    const uint32_t so0 = sw_off(r0, c0),       so1 = sw_off(r0 + 64, c0);
    const uint32_t so2 = sw_off(r0 + 128, c0), so3 = sw_off(r0 + 192, c0);

    // ldmatrix per-thread addressing
    const int id = lid >> 3, rin = lid & 7;
    const int arow = warpM * 32 + (id & 1) * 8 + rin;
    const int acol = (id >> 1);
    const int brow = warpN * 64 + (id >> 1) * 8 + rin;
    const int bcol = (id & 1);

    float acc[2][8][4];
#pragma unroll
    for (int mt = 0; mt < 2; mt++)
#pragma unroll
        for (int nf = 0; nf < 8; nf++)
#pragma unroll
            for (int q = 0; q < 4; q++) acc[mt][nf][q] = 0.0f;

    const int NCH = K / 64;

    auto ISSUE = [&](int ch) {
        const int kc = ch * 64;
        const uint32_t dst = sb + (uint32_t)(ch & 1) * STG;
        cpa16(dst + S_AHI + so0, gAh + kc);
        cpa16(dst + S_AHI + so1, gAh + kc + s64);
        cpa16(dst + S_ALO + so0, gAl + kc);
        cpa16(dst + S_ALO + so1, gAl + kc + s64);
        cpa16(dst + S_BHI + so0, gBh + kc);
        cpa16(dst + S_BHI + so1, gBh + kc + s64);
        cpa16(dst + S_BHI + so2, gBh + kc + 2 * s64);
        cpa16(dst + S_BHI + so3, gBh + kc + 3 * s64);
        cpa16(dst + S_BLO + so0, gBl + kc);
        cpa16(dst + S_BLO + so1, gBl + kc + s64);
        cpa16(dst + S_BLO + so2, gBl + kc + 2 * s64);
        cpa16(dst + S_BLO + so3, gBl + kc + 3 * s64);
        CP_COMMIT();
    };

    ISSUE(0);
    CP_WAIT0();
    __syncthreads();

    for (int ch = 0; ch < NCH; ch++) {
        if (ch + 1 < NCH) ISSUE(ch + 1);
        const uint32_t bufb = sb + (uint32_t)(ch & 1) * STG;

#pragma unroll
        for (int kk = 0; kk < 4; kk++) {
            uint32_t ah[2][4], al[2][4];
#pragma unroll
            for (int mt = 0; mt < 2; mt++) {
                uint32_t ao = sw_off(arow + mt * 16, acol + kk * 2);
                ldsm_x4(ah[mt], bufb + S_AHI + ao);
                ldsm_x4(al[mt], bufb + S_ALO + ao);
            }
#pragma unroll
            for (int g = 0; g < 2; g++) {   // two groups of 2 n16-tiles
                uint32_t bh[2][4], bl[2][4];
#pragma unroll
                for (int j = 0; j < 2; j++) {
                    uint32_t bo = sw_off(brow + (g * 2 + j) * 16, bcol + kk * 2);
                    ldsm_x4(bh[j], bufb + S_BHI + bo);
                    ldsm_x4(bl[j], bufb + S_BLO + bo);
                }
#pragma unroll
                for (int mt = 0; mt < 2; mt++)
#pragma unroll
                    for (int j = 0; j < 2; j++)
#pragma unroll
                        for (int h = 0; h < 2; h++) {
                            float* c = acc[mt][(g * 2 + j) * 2 + h];
                            mma_bf16(c, ah[mt], &bh[j][h * 2]);   // hi*hi
                            mma_bf16(c, al[mt], &bh[j][h * 2]);   // lo*hi
                            mma_bf16(c, ah[mt], &bl[j][h * 2]);   // hi*lo
                        }
            }
        }
        if (ch + 1 < NCH) {
            CP_WAIT0();
            __syncthreads();
        }
    }

    // ---- epilogue (register fragments) ----
    float beta1 = 0.f, beta2 = 0.f, wt0 = 0.f, invb3 = 0.f, om2 = 0.f;
    int T = 0;
    if (mode == MODE_SCAN) {
        beta1 = sigmoid_acc(b_taus[0]);
        beta2 = sigmoid_acc(b_taus[1]);
        float beta3 = sigmoid_acc(b_taus[2]);
        T     = *Tp;
        invb3 = 1.0f / beta3;
        om2   = 1.0f - beta2;
        wt0   = (1.0f - beta3) * powf(beta3, (float)(T - 1));
    }

    const int mrow = m0 + warpM * 32 + (lid >> 2);
    const int ncol = n0 + warpN * 64 + (lid & 3) * 2;

#pragma unroll
    for (int mt = 0; mt < 2; mt++) {
#pragma unroll
        for (int nf = 0; nf < 8; nf++) {
            const int col = ncol + nf * 8;
#pragma unroll
            for (int pair = 0; pair < 2; pair++) {
                const int row = mrow + mt * 16 + pair * 8;
                float v0 = acc[mt][nf][pair * 2 + 0];
                float v1 = acc[mt][nf][pair * 2 + 1];
                size_t base = (size_t)row * N + col;

                if (mode == MODE_PART) {
                    float* Cz = Cf + (size_t)blockIdx.z * M * N;
                    *(float2*)(Cz + base) = make_float2(v0, v1);
                    continue;
                }

                float bv0 = __ldg(&bias[col]), bv1 = __ldg(&bias[col + 1]);
                float o0, o1;
                if (mode == MODE_RELU) {
                    o0 = fmaxf(v0 + bv0, 0.0f);
                    o1 = fmaxf(v1 + bv1, 0.0f);
                } else { // MODE_SCAN
                    float s20 = 0.f, a0 = 0.f, s21 = 0.f, a1 = 0.f;
                    float bp = beta1, wt = wt0;
                    for (int t = 0; t < T; t++) {
                        float c1m = 1.0f - bp;
                        float d0 = fmaxf(fmaf(c1m, v0, bv0), 0.0f);
                        float d1 = fmaxf(fmaf(c1m, v1, bv1), 0.0f);
                        s20 = fmaf(beta2, s20, om2 * d0);
                        s21 = fmaf(beta2, s21, om2 * d1);
                        a0 = fmaf(wt, s20, a0);
                        a1 = fmaf(wt, s21, a1);
                        bp *= beta1;
                        wt *= invb3;
                    }
                    o0 = a0; o1 = a1;
                }
                bf16 h0 = __float2bfloat16(o0), h1 = __float2bfloat16(o1);
                bf16 l0 = __float2bfloat16(o0 - __bfloat162float(h0));
                bf16 l1 = __float2bfloat16(o1 - __bfloat162float(h1));
                uint32_t hp = (uint32_t)__bfloat16_as_ushort(h0) |
                              ((uint32_t)__bfloat16_as_ushort(h1) << 16);
                uint32_t lp = (uint32_t)__bfloat16_as_ushort(l0) |
                              ((uint32_t)__bfloat16_as_ushort(l1) << 16);
                *(uint32_t*)(OutHi + base) = hp;
                *(uint32_t*)(OutLo + base) = lp;
            }
        }
    }
}

// out[i] = (1 - beta3^T) * b3[i % N] + sum_z part[z][i]
__global__ void __launch_bounds__(256)
reduce_out(const float* __restrict__ part, const float* __restrict__ b3,
           float* __restrict__ out, int total, int N,
           const float* __restrict__ b_taus, const int* __restrict__ Tp)
{
    int i = (blockIdx.x * blockDim.x + threadIdx.x) * 4;
    if (i >= total) return;
    float beta3  = sigmoid_acc(b_taus[2]);
    float bscale = 1.0f - powf(beta3, (float)(*Tp));
    float4 bb = *(const float4*)(b3 + (i % N));
    float4 s  = make_float4(bscale * bb.x, bscale * bb.y, bscale * bb.z, bscale * bb.w);
#pragma unroll
    for (int z = 0; z < KSPLIT; z++) {
        float4 p = *(const float4*)(part + (size_t)z * total + i);
        s.x += p.x; s.y += p.y; s.z += p.z; s.w += p.w;
    }
    *(float4*)(out + i) = s;
}

extern "C" void kernel_launch(void* const* d_in, const int* in_sizes, int n_in,
                              void* d_out, int out_size)
{
    const float* x     = (const float*)d_in[0];
    const float* W1    = (const float*)d_in[1];
    const float* b1    = (const float*)d_in[2];
    const float* W2    = (const float*)d_in[3];
    const float* b2    = (const float*)d_in[4];
    const float* W3    = (const float*)d_in[5];
    const float* b3    = (const float*)d_in[6];
    const float* btaus = (const float*)d_in[7];
    const int*   Tp    = (const int*)d_in[8];

    const int H1    = in_sizes[2];
    const int D_IN  = in_sizes[1] / H1;
    const int B     = in_sizes[0] / D_IN;
    const int H2    = in_sizes[4];
    const int D_OUT = in_sizes[6];

    bf16 *xhi, *xlo, *w1hi, *w1lo, *w2hi, *w2lo, *w3hi, *w3lo;
    bf16 *d1hi, *d1lo, *s2hi, *s2lo;
    float* part;
    cudaGetSymbolAddress((void**)&xhi,  g_xhi);  cudaGetSymbolAddress((void**)&xlo,  g_xlo);
    cudaGetSymbolAddress((void**)&w1hi, g_w1hi); cudaGetSymbolAddress((void**)&w1lo, g_w1lo);
    cudaGetSymbolAddress((void**)&w2hi, g_w2hi); cudaGetSymbolAddress((void**)&w2lo, g_w2lo);
    cudaGetSymbolAddress((void**)&w3hi, g_w3hi); cudaGetSymbolAddress((void**)&w3lo, g_w3lo);
    cudaGetSymbolAddress((void**)&d1hi, g_d1hi); cudaGetSymbolAddress((void**)&d1lo, g_d1lo);
    cudaGetSymbolAddress((void**)&s2hi, g_s2hi); cudaGetSymbolAddress((void**)&s2lo, g_s2lo);
    cudaGetSymbolAddress((void**)&part, g_part);

    float* out = (float*)d_out;

    const int SMEM = 2 * 98304;   // 196,608 B
    cudaFuncSetAttribute(tc_gemm, cudaFuncAttributeMaxDynamicSharedMemorySize, SMEM);

    // 0) split all inputs into bf16 hi/lo, single launch (8 elems/thread)
    {
        int nb0 = (B * D_IN)   / 2048;
        int nb1 = (H1 * D_IN)  / 2048;
        int nb2 = (H2 * H1)    / 2048;
        int nb3 = (D_OUT * H2) / 2048;
        convert_split4<<<nb0 + nb1 + nb2 + nb3, 256>>>(
            x,  xhi,  xlo,  nb0,
            W1, w1hi, w1lo, nb1,
            W2, w2hi, w2lo, nb2,
            W3, w3hi, w3lo, nb3);
    }
    // 1) d1 = relu(x @ W1^T + b1) -> bf16 hi/lo           [B, H1]
    {
        dim3 grid(H1 / 256, B / 128, 1);
        tc_gemm<<<grid, 512, SMEM>>>(xhi, xlo, w1hi, w1lo, b1, nullptr, d1hi, d1lo,
                                     B, H1, D_IN, D_IN, MODE_RELU, btaus, Tp);
    }
    // 2) s2acc = scan(d1 @ W2^T, b2) -> bf16 hi/lo        [B, H2]
    {
        dim3 grid(H2 / 256, B / 128, 1);
        tc_gemm<<<grid, 512, SMEM>>>(d1hi, d1lo, w2hi, w2lo, b2, nullptr, s2hi, s2lo,
                                     B, H2, H1, H1, MODE_SCAN, btaus, Tp);
    }
    // 3) split-K partials of s2acc @ W3^T                 [KSPLIT][B, D_OUT]
    {
        dim3 grid(D_OUT / 256, B / 128, KSPLIT);
        tc_gemm<<<grid, 512, SMEM>>>(s2hi, s2lo, w3hi, w3lo, nullptr, part, nullptr, nullptr,
                                     B, D_OUT, H2 / KSPLIT, H2, MODE_PART, btaus, Tp);
    }
    // 4) out = (1-b3^T) b3 + sum partials                 [B, D_OUT]
    {
        int total = B * D_OUT;
        reduce_out<<<(total / 4 + 255) / 256, 256>>>(part, b3, out, total, D_OUT, btaus, Tp);
    }
    (void)n_in; (void)out_size;
}